// round 3
// baseline (speedup 1.0000x reference)
#include <cuda_runtime.h>
#include <cstdint>

#define ITEMS_TOTAL 50000
#define DIM         64
#define BATCH       16
#define NPG         50
#define VEC4_PER_ROW (DIM / 4)   // 16 float4 per row

// Per-row batch bitmask + last-occurrence position table.
// Zero-initialized at load; every kernel_launch call clears its own touched
// entries at the START of prep (same node indices every replay), so state is
// clean and deterministic for each call.
__device__ unsigned int g_mask[ITEMS_TOTAL];          // bit b: row touched in graph b
__device__ int          g_pos[ITEMS_TOTAL * BATCH];   // last position j for (row, b)

// Prep: single CTA. Detect nodes dtype, clear this call's mask entries,
// then set bits + positions for last occurrences.
__global__ void __launch_bounds__(800)
prep_kernel(const void* __restrict__ nodes_raw) {
    __shared__ int s_not64;
    if (threadIdx.x == 0) s_not64 = 0;
    __syncthreads();
    const int* a32 = (const int*)nodes_raw;
    for (int k = threadIdx.x; k < 400; k += blockDim.x) {
        if (a32[2 * k + 1] != 0) s_not64 = 1;   // benign race
    }
    __syncthreads();
    const bool is64 = (s_not64 == 0);
    const long long* a64 = (const long long*)nodes_raw;

    int j = threadIdx.x;                         // 0..799
    if (j >= BATCH * NPG) return;
    long long idx = is64 ? a64[j] : (long long)a32[j];

    // clear (races benign: all write 0)
    g_mask[idx] = 0u;
    __syncthreads();

    int b  = j / NPG;
    int jl = j % NPG;
    // last-occurrence: skip if a later position in this graph has same idx
    bool last = true;
    for (int jj = jl + 1; jj < NPG; jj++) {
        long long other = is64 ? a64[b * NPG + jj] : (long long)a32[b * NPG + jj];
        if (other == idx) { last = false; break; }
    }
    if (last) {
        atomicOr(&g_mask[idx], 1u << b);
        g_pos[(int)idx * BATCH + b] = j;
    }
}

// Fused broadcast + gated update.
// Thread t handles float4 lane (t&15) of row (t>>4); writes all 16 batches.
__global__ void __launch_bounds__(256)
fused_kernel(const float4* __restrict__ emb4,
             const float*  __restrict__ feat,    // (BATCH*NPG, DIM)
             const float*  __restrict__ alpha,   // (ITEMS_TOTAL, 1)
             float4*       __restrict__ out4) {  // (BATCH, ITEMS_TOTAL, DIM/4)
    const long long n4 = (long long)ITEMS_TOTAL * VEC4_PER_ROW;  // 800,000
    long long t = (long long)blockIdx.x * blockDim.x + threadIdx.x;
    if (t >= n4) return;
    int i    = (int)(t >> 4);
    int lane = (int)(t & 15);
    float4 v = emb4[t];
    unsigned m = g_mask[i];
    if (m == 0u) {
#pragma unroll
        for (int b = 0; b < BATCH; b++) {
            out4[(long long)b * n4 + t] = v;
        }
    } else {
        float a  = alpha[i];
        float na = 1.0f - a;
#pragma unroll
        for (int b = 0; b < BATCH; b++) {
            float4 w = v;
            if ((m >> b) & 1u) {
                int j = g_pos[i * BATCH + b];
                const float4* f4 = reinterpret_cast<const float4*>(feat + (long long)j * DIM);
                float4 f = f4[lane];
                w.x = fmaf(a, f.x, na * v.x);
                w.y = fmaf(a, f.y, na * v.y);
                w.z = fmaf(a, f.z, na * v.z);
                w.w = fmaf(a, f.w, na * v.w);
            }
            out4[(long long)b * n4 + t] = w;
        }
    }
}

extern "C" void kernel_launch(void* const* d_in, const int* in_sizes, int n_in,
                              void* d_out, int out_size) {
    // 0: nodes (int32/int64)  1: nodes_output f32  2: emb_table f32  3: alpha f32
    const void*  nodes = d_in[0];
    const float* feat  = (const float*)d_in[1];
    const float* emb   = (const float*)d_in[2];
    const float* alpha = (const float*)d_in[3];
    float*       out   = (float*)d_out;

    prep_kernel<<<1, 800>>>(nodes);

    const long long n4 = (long long)ITEMS_TOTAL * VEC4_PER_ROW;
    int threads = 256;
    int blocks  = (int)((n4 + threads - 1) / threads);
    fused_kernel<<<blocks, threads>>>(
        reinterpret_cast<const float4*>(emb), feat, alpha,
        reinterpret_cast<float4*>(out));
}

// round 4
// speedup vs baseline: 1.2947x; 1.2947x over previous
#include <cuda_runtime.h>
#include <cstdint>

#define ITEMS_TOTAL 50000
#define DIM         64
#define BATCH       16
#define NPG         50
#define VEC4_PER_ROW (DIM / 4)   // 16 float4 per row
#define ROWS_PER_CTA 16
#define THREADS      256         // 16 rows x 16 lanes

// Single fused kernel: broadcast emb_table to all 16 batch slices, blending
// in the gated update for touched rows. Node bookkeeping (dtype detection,
// last-occurrence positions) is recomputed per-CTA in shared memory — no
// auxiliary launches, no persistent device state.
__global__ void __launch_bounds__(THREADS)
fused_kernel(const float4* __restrict__ emb4,
             const float*  __restrict__ feat,      // (BATCH*NPG, DIM)
             const float*  __restrict__ alpha,     // (ITEMS_TOTAL, 1)
             const void*   __restrict__ nodes_raw, // int32 or int64, 800 entries
             float4*       __restrict__ out4) {    // (BATCH, ITEMS_TOTAL, DIM/4)
    __shared__ int s_stage[BATCH * NPG];            // raw first 3200 bytes
    __shared__ int s_idx[BATCH * NPG];              // node indices as int32
    __shared__ int s_pos[ROWS_PER_CTA][BATCH + 1];  // last pos per (row,b); +1 pad
    __shared__ int s_not64;

    const int tid = threadIdx.x;
    const int* a32 = (const int*)nodes_raw;

    if (tid == 0) s_not64 = 0;

    // Phase 1a: stage first 3200 bytes (valid under both dtypes).
    for (int k = tid; k < BATCH * NPG; k += THREADS) s_stage[k] = a32[k];
    __syncthreads();

    // Phase 1b: dtype detection — int64 little-endian with values < 50000
    // has all-zero high words among the first 400 pairs.
    for (int k = tid; k < 400; k += THREADS) {
        if (s_stage[2 * k + 1] != 0) s_not64 = 1;   // benign race
    }
    __syncthreads();
    const bool is64 = (s_not64 == 0);

    // Phase 1c: compact to int32 indices.
    for (int k = tid; k < BATCH * NPG; k += THREADS) {
        int v;
        if (is64) {
            v = (k < 400) ? s_stage[2 * k]
                          : a32[2 * k];  // in-bounds: int64 buffer is 6400 B
        } else {
            v = s_stage[k];
        }
        s_idx[k] = v;
    }
    __syncthreads();

    // Phase 2: thread (r, b) finds last occurrence of its row in graph b.
    const int r    = tid >> 4;     // 0..15 local row
    const int b_id = tid & 15;     // 0..15 batch
    const int row  = blockIdx.x * ROWS_PER_CTA + r;
    {
        int p = -1;
        const int base = b_id * NPG;
#pragma unroll 10
        for (int jj = 0; jj < NPG; jj++) {
            if (s_idx[base + jj] == row) p = base + jj;   // forward scan => last wins
        }
        s_pos[r][b_id] = p;
    }
    __syncthreads();

    // Phase 3: broadcast + blend. Thread (r, lane): lane = b_id reused as lane.
    const int lane = b_id;
    const long long n4 = (long long)ITEMS_TOTAL * VEC4_PER_ROW;     // 800,000
    const long long t  = (long long)row * VEC4_PER_ROW + lane;
    float4 v = emb4[t];

    // Check whether any batch touches this row; load alpha only then.
    bool touched = false;
#pragma unroll
    for (int b = 0; b < BATCH; b++) touched |= (s_pos[r][b] >= 0);

    if (!touched) {
#pragma unroll
        for (int b = 0; b < BATCH; b++) {
            __stcs(&out4[(long long)b * n4 + t], v);
        }
    } else {
        const float a  = alpha[row];
        const float na = 1.0f - a;
#pragma unroll
        for (int b = 0; b < BATCH; b++) {
            float4 w = v;
            int p = s_pos[r][b];
            if (p >= 0) {
                const float4* f4 =
                    reinterpret_cast<const float4*>(feat + (long long)p * DIM);
                float4 f = f4[lane];
                w.x = fmaf(a, f.x, na * v.x);
                w.y = fmaf(a, f.y, na * v.y);
                w.z = fmaf(a, f.z, na * v.z);
                w.w = fmaf(a, f.w, na * v.w);
            }
            __stcs(&out4[(long long)b * n4 + t], w);
        }
    }
}

extern "C" void kernel_launch(void* const* d_in, const int* in_sizes, int n_in,
                              void* d_out, int out_size) {
    // 0: nodes (int32/int64)  1: nodes_output f32  2: emb_table f32  3: alpha f32
    const void*  nodes = d_in[0];
    const float* feat  = (const float*)d_in[1];
    const float* emb   = (const float*)d_in[2];
    const float* alpha = (const float*)d_in[3];
    float*       out   = (float*)d_out;

    const int blocks = ITEMS_TOTAL / ROWS_PER_CTA;   // 3125
    fused_kernel<<<blocks, THREADS>>>(
        reinterpret_cast<const float4*>(emb), feat, alpha, nodes,
        reinterpret_cast<float4*>(out));
}

// round 5
// speedup vs baseline: 1.3731x; 1.0606x over previous
#include <cuda_runtime.h>
#include <cstdint>

#define ITEMS_TOTAL 50000
#define DIM         64
#define BATCH       16
#define NPG         50
#define VEC4_PER_ROW (DIM / 4)   // 16 float4 per row
#define ROWS_PER_CTA 32
#define THREADS      512         // 32 rows x 16 lanes

// Single fused kernel: broadcast emb_table to all 16 batch slices, blending
// the gated update for touched rows. Node bookkeeping recomputed per-CTA in
// shared memory; emb read prefetched ahead of the prologue to hide it.
__global__ void __launch_bounds__(THREADS)
fused_kernel(const float4* __restrict__ emb4,
             const float*  __restrict__ feat,      // (BATCH*NPG, DIM)
             const float*  __restrict__ alpha,     // (ITEMS_TOTAL, 1)
             const void*   __restrict__ nodes_raw, // int32 or int64, 800 entries
             float4*       __restrict__ out4) {    // (BATCH, ITEMS_TOTAL, DIM/4)
    __shared__ int s_stage[BATCH * NPG];            // raw first 3200 bytes
    __shared__ int s_idx[BATCH * NPG];              // node indices as int32
    __shared__ int s_pos[ROWS_PER_CTA][BATCH + 1];  // last pos per (row,b); pad
    __shared__ int s_not64;
    __shared__ int s_any;                           // any node in this CTA's rows?

    const int tid  = threadIdx.x;
    const int r    = tid >> 4;                      // 0..31 local row
    const int b_id = tid & 15;                      // 0..15 batch / lane
    const int row  = blockIdx.x * ROWS_PER_CTA + r;
    const int row_base = blockIdx.x * ROWS_PER_CTA;
    const bool row_ok = (row < ITEMS_TOTAL);

    // ---- Prefetch emb row chunk (independent of smem phases) ----
    const long long n4 = (long long)ITEMS_TOTAL * VEC4_PER_ROW;   // 800,000
    const long long t  = (long long)row * VEC4_PER_ROW + b_id;
    float4 v;
    if (row_ok) v = emb4[t];

    const int* a32 = (const int*)nodes_raw;
    if (tid == 0) { s_not64 = 0; s_any = 0; }

    // Phase 1a: stage first 3200 bytes (valid under both dtypes).
    for (int k = tid; k < BATCH * NPG; k += THREADS) s_stage[k] = a32[k];
    __syncthreads();

    // Phase 1b: dtype detection — int64 LE with values < 50000 has all-zero
    // high words in the first 400 pairs.
    for (int k = tid; k < 400; k += THREADS) {
        if (s_stage[2 * k + 1] != 0) s_not64 = 1;   // benign race
    }
    __syncthreads();
    const bool is64 = (s_not64 == 0);

    // Phase 1c: compact to int32 indices; flag if any falls in our row window.
    for (int k = tid; k < BATCH * NPG; k += THREADS) {
        int val;
        if (is64) {
            val = (k < 400) ? s_stage[2 * k] : a32[2 * k];  // int64 buf = 6400 B
        } else {
            val = s_stage[k];
        }
        s_idx[k] = val;
        if ((unsigned)(val - row_base) < (unsigned)ROWS_PER_CTA) s_any = 1;
    }
    __syncthreads();

    if (s_any) {
        // Phase 2: thread (r, b) finds last occurrence of its row in graph b.
        int p = -1;
        const int base = b_id * NPG;
#pragma unroll 10
        for (int jj = 0; jj < NPG; jj++) {
            if (s_idx[base + jj] == row) p = base + jj;  // forward scan => last
        }
        s_pos[r][b_id] = p;
        __syncthreads();

        if (row_ok) {
            bool touched = false;
#pragma unroll
            for (int b = 0; b < BATCH; b++) touched |= (s_pos[r][b] >= 0);

            if (!touched) {
#pragma unroll
                for (int b = 0; b < BATCH; b++)
                    __stcs(&out4[(long long)b * n4 + t], v);
            } else {
                const float a  = alpha[row];
                const float na = 1.0f - a;
#pragma unroll
                for (int b = 0; b < BATCH; b++) {
                    float4 w = v;
                    int p2 = s_pos[r][b];
                    if (p2 >= 0) {
                        const float4* f4 = reinterpret_cast<const float4*>(
                            feat + (long long)p2 * DIM);
                        float4 f = f4[b_id];
                        w.x = fmaf(a, f.x, na * v.x);
                        w.y = fmaf(a, f.y, na * v.y);
                        w.z = fmaf(a, f.z, na * v.z);
                        w.w = fmaf(a, f.w, na * v.w);
                    }
                    __stcs(&out4[(long long)b * n4 + t], w);
                }
            }
        }
    } else if (row_ok) {
        // Untouched CTA: pure 16-way broadcast store.
#pragma unroll
        for (int b = 0; b < BATCH; b++)
            __stcs(&out4[(long long)b * n4 + t], v);
    }
}

extern "C" void kernel_launch(void* const* d_in, const int* in_sizes, int n_in,
                              void* d_out, int out_size) {
    // 0: nodes (int32/int64)  1: nodes_output f32  2: emb_table f32  3: alpha f32
    const void*  nodes = d_in[0];
    const float* feat  = (const float*)d_in[1];
    const float* emb   = (const float*)d_in[2];
    const float* alpha = (const float*)d_in[3];
    float*       out   = (float*)d_out;

    const int blocks = (ITEMS_TOTAL + ROWS_PER_CTA - 1) / ROWS_PER_CTA;  // 1563
    fused_kernel<<<blocks, THREADS>>>(
        reinterpret_cast<const float4*>(emb), feat, alpha, nodes,
        reinterpret_cast<float4*>(out));
}